// round 1
// baseline (speedup 1.0000x reference)
#include <cuda_runtime.h>
#include <math.h>
#include <float.h>

#define SLEN 2048
#define HID  4096
#define NQH  32
#define NKVH 8
#define HDIM 128
#define QKVN 6144   // (32 + 2*8) * 128
#define EPSV 1e-6f

// Scratch (allocation-free rule: __device__ globals)
__device__ float g_qkv[(size_t)SLEN * QKVN];                 // 50 MB
__device__ float g_scores[(size_t)NQH * SLEN * SLEN];        // 537 MB
__device__ float g_attn[(size_t)SLEN * HID];                 // 34 MB

// ---------------------------------------------------------------------------
// Generic 128x128x8 SGEMM, 256 threads, 8x8 microtile with split row/col
// mapping (rows {tr*4..+3, 64+tr*4..+3}, cols likewise) for conflict-free
// float4 LDS in the inner loop.
//   NT        : C = A * B^T (B stored row-major [N,K]) — used for Q@K^T
//   MASKSCALE : epilogue applies *scale and causal mask (col>row -> -inf);
//               fully-masked tiles short-circuit to a -inf fill
//   CAUSALK   : K-loop clamped to row0+BM (A is lower-triangular-ish) — P@V
// Batch (blockIdx.z): A += z*aStride, B += (z/bDiv)*bStride, C += z*cStride
// ---------------------------------------------------------------------------
template<bool NT, bool MASKSCALE, bool CAUSALK>
__global__ __launch_bounds__(256) void sgemm(
    const float* __restrict__ Abase, int lda, long aStride,
    const float* __restrict__ Bbase, int ldb, long bStride, int bDiv,
    float* __restrict__ Cbase, int ldc, long cStride,
    int M, int N, int K, float scale)
{
    constexpr int BM = 128, BN = 128, BK = 8;
    __shared__ float As[BK][BM];
    __shared__ float Bs[BK][BN];

    const int z = blockIdx.z;
    const float* A = Abase + (long)z * aStride;
    const float* B = Bbase + (long)(z / bDiv) * bStride;
    float* C = Cbase + (long)z * cStride;

    const int row0 = blockIdx.y * BM;
    const int col0 = blockIdx.x * BN;
    const int tid = threadIdx.x;
    const int tr = tid >> 4;   // 0..15
    const int tc = tid & 15;   // 0..15

    if (MASKSCALE) {
        // Block entirely above the diagonal: pure -inf fill, no compute.
        if (col0 > row0 + BM - 1) {
            const float4 ninf = make_float4(-INFINITY, -INFINITY, -INFINITY, -INFINITY);
            #pragma unroll
            for (int i = 0; i < 8; i++) {
                int r = row0 + ((i < 4) ? (tr * 4 + i) : (64 + tr * 4 + (i - 4)));
                *reinterpret_cast<float4*>(&C[(long)r * ldc + col0 + tc * 4]) = ninf;
                *reinterpret_cast<float4*>(&C[(long)r * ldc + col0 + 64 + tc * 4]) = ninf;
            }
            return;
        }
    }

    float acc[8][8];
    #pragma unroll
    for (int i = 0; i < 8; i++)
        #pragma unroll
        for (int j = 0; j < 8; j++)
            acc[i][j] = 0.f;

    int kEnd = K;
    if (CAUSALK) {
        int ke = row0 + BM;
        kEnd = (ke < K) ? ke : K;
    }

    for (int k0 = 0; k0 < kEnd; k0 += BK) {
        // --- load A tile (BMxBK) transposed into As[k][m] ---
        {
            int r = tid >> 1;
            int c = (tid & 1) * 4;
            float4 v = *reinterpret_cast<const float4*>(&A[(long)(row0 + r) * lda + k0 + c]);
            As[c + 0][r] = v.x; As[c + 1][r] = v.y; As[c + 2][r] = v.z; As[c + 3][r] = v.w;
        }
        // --- load B tile into Bs[k][n] ---
        if (!NT) {
            int r = tid >> 5;            // k row 0..7
            int c = (tid & 31) * 4;      // n col
            float4 v = *reinterpret_cast<const float4*>(&B[(long)(k0 + r) * ldb + col0 + c]);
            *reinterpret_cast<float4*>(&Bs[r][c]) = v;
        } else {
            int r = tid >> 1;            // n row 0..127
            int c = (tid & 1) * 4;       // k col
            float4 v = *reinterpret_cast<const float4*>(&B[(long)(col0 + r) * ldb + k0 + c]);
            Bs[c + 0][r] = v.x; Bs[c + 1][r] = v.y; Bs[c + 2][r] = v.z; Bs[c + 3][r] = v.w;
        }
        __syncthreads();

        #pragma unroll
        for (int kk = 0; kk < BK; kk++) {
            float a[8], b[8];
            float4 t;
            t = *reinterpret_cast<const float4*>(&As[kk][tr * 4]);
            a[0] = t.x; a[1] = t.y; a[2] = t.z; a[3] = t.w;
            t = *reinterpret_cast<const float4*>(&As[kk][64 + tr * 4]);
            a[4] = t.x; a[5] = t.y; a[6] = t.z; a[7] = t.w;
            t = *reinterpret_cast<const float4*>(&Bs[kk][tc * 4]);
            b[0] = t.x; b[1] = t.y; b[2] = t.z; b[3] = t.w;
            t = *reinterpret_cast<const float4*>(&Bs[kk][64 + tc * 4]);
            b[4] = t.x; b[5] = t.y; b[6] = t.z; b[7] = t.w;
            #pragma unroll
            for (int i = 0; i < 8; i++)
                #pragma unroll
                for (int j = 0; j < 8; j++)
                    acc[i][j] = fmaf(a[i], b[j], acc[i][j]);
        }
        __syncthreads();
    }

    // --- epilogue ---
    #pragma unroll
    for (int i = 0; i < 8; i++) {
        int r = row0 + ((i < 4) ? (tr * 4 + i) : (64 + tr * 4 + (i - 4)));
        #pragma unroll
        for (int half = 0; half < 2; half++) {
            float vals[4];
            #pragma unroll
            for (int j = 0; j < 4; j++) {
                float v = acc[i][half * 4 + j];
                if (MASKSCALE) {
                    int cidx = col0 + half * 64 + tc * 4 + j;
                    v = (cidx <= r) ? v * scale : -INFINITY;
                }
                vals[j] = v;
            }
            float4 o = make_float4(vals[0], vals[1], vals[2], vals[3]);
            *reinterpret_cast<float4*>(&C[(long)r * ldc + col0 + half * 64 + tc * 4]) = o;
        }
    }
}

// ---------------------------------------------------------------------------
// Fused RMSNorm (per head over HD=128) + RoPE, in place on g_qkv.
// Grid: (SLEN, NQH+NKVH), 128 threads.
// ---------------------------------------------------------------------------
__global__ __launch_bounds__(128) void rmsnorm_rope(
    const float* __restrict__ cosT, const float* __restrict__ sinT,
    const float* __restrict__ q_gamma, const float* __restrict__ k_gamma)
{
    const int s = blockIdx.x;
    const int h = blockIdx.y;           // 0..39
    float* x;
    const float* gamma;
    if (h < NQH) { x = g_qkv + (size_t)s * QKVN + h * HDIM;              gamma = q_gamma; }
    else         { x = g_qkv + (size_t)s * QKVN + NQH * HDIM + (h - NQH) * HDIM; gamma = k_gamma; }

    const int tid = threadIdx.x;        // 0..127
    float v = x[tid];
    float sq = v * v;
    #pragma unroll
    for (int o = 16; o > 0; o >>= 1) sq += __shfl_xor_sync(0xffffffffu, sq, o);
    __shared__ float ws[4];
    if ((tid & 31) == 0) ws[tid >> 5] = sq;
    __syncthreads();
    float total = ws[0] + ws[1] + ws[2] + ws[3];
    float rinv = rsqrtf(total * (1.0f / HDIM) + EPSV);

    __shared__ float xn[HDIM];
    xn[tid] = v * rinv * gamma[tid];
    __syncthreads();

    if (tid < 64) {
        float c = cosT[(size_t)s * 64 + tid];
        float sn = sinT[(size_t)s * 64 + tid];
        float x1 = xn[tid];
        float x2 = xn[tid + 64];
        x[tid]      = x1 * c - x2 * sn;
        x[tid + 64] = x2 * c + x1 * sn;
    }
}

// ---------------------------------------------------------------------------
// Row softmax over SLEN (masked entries hold -inf -> exp()=0).
// Grid: (SLEN rows, NQH heads), 256 threads.
// ---------------------------------------------------------------------------
__global__ __launch_bounds__(256) void softmax_rows(float* __restrict__ scores)
{
    float* p = scores + ((size_t)blockIdx.y * SLEN + blockIdx.x) * SLEN;
    const int tid = threadIdx.x;
    __shared__ float red[8];

    float m = -FLT_MAX;
    for (int j = tid; j < SLEN; j += 256) m = fmaxf(m, p[j]);
    #pragma unroll
    for (int o = 16; o > 0; o >>= 1) m = fmaxf(m, __shfl_xor_sync(0xffffffffu, m, o));
    if ((tid & 31) == 0) red[tid >> 5] = m;
    __syncthreads();
    if (tid < 32) {
        float mm = (tid < 8) ? red[tid] : -FLT_MAX;
        #pragma unroll
        for (int o = 4; o > 0; o >>= 1) mm = fmaxf(mm, __shfl_xor_sync(0xffffffffu, mm, o));
        if (tid == 0) red[0] = mm;
    }
    __syncthreads();
    m = red[0];
    __syncthreads();

    float s = 0.f;
    for (int j = tid; j < SLEN; j += 256) { float e = expf(p[j] - m); p[j] = e; s += e; }
    #pragma unroll
    for (int o = 16; o > 0; o >>= 1) s += __shfl_xor_sync(0xffffffffu, s, o);
    if ((tid & 31) == 0) red[tid >> 5] = s;
    __syncthreads();
    if (tid < 32) {
        float ss = (tid < 8) ? red[tid] : 0.f;
        #pragma unroll
        for (int o = 4; o > 0; o >>= 1) ss += __shfl_xor_sync(0xffffffffu, ss, o);
        if (tid == 0) red[0] = ss;
    }
    __syncthreads();
    float inv = 1.f / red[0];
    for (int j = tid; j < SLEN; j += 256) p[j] *= inv;
}

// ---------------------------------------------------------------------------
// Inputs (metadata order): positions, hidden_states, Wqkv, Wo, q_gamma,
// k_gamma, cos, sin. Output: [2048, 4096] fp32.
// ---------------------------------------------------------------------------
extern "C" void kernel_launch(void* const* d_in, const int* in_sizes, int n_in,
                              void* d_out, int out_size)
{
    (void)in_sizes; (void)n_in; (void)out_size;
    const float* hidden = (const float*)d_in[1];
    const float* Wqkv   = (const float*)d_in[2];
    const float* Wo     = (const float*)d_in[3];
    const float* qg     = (const float*)d_in[4];
    const float* kg     = (const float*)d_in[5];
    const float* cosT   = (const float*)d_in[6];
    const float* sinT   = (const float*)d_in[7];
    float* out = (float*)d_out;

    float *qkv, *scores, *attn;
    cudaGetSymbolAddress((void**)&qkv, g_qkv);
    cudaGetSymbolAddress((void**)&scores, g_scores);
    cudaGetSymbolAddress((void**)&attn, g_attn);

    // 1) QKV projection: [2048,4096] @ [4096,6144]
    sgemm<false, false, false><<<dim3(QKVN / 128, SLEN / 128, 1), 256>>>(
        hidden, HID, 0, Wqkv, QKVN, 0, 1, qkv, QKVN, 0, SLEN, QKVN, HID, 1.f);

    // 2) RMSNorm + RoPE in place on Q and K heads
    rmsnorm_rope<<<dim3(SLEN, NQH + NKVH), 128>>>(cosT, sinT, qg, kg);

    // 3) Scores = Q @ K^T * HD^-0.5 with causal mask (per head, GQA z/4)
    sgemm<true, true, false><<<dim3(SLEN / 128, SLEN / 128, NQH), 256>>>(
        qkv, QKVN, HDIM,
        qkv + NQH * HDIM, QKVN, HDIM, 4,
        scores, SLEN, (long)SLEN * SLEN,
        SLEN, SLEN, HDIM, 0.08838834764831845f);

    // 4) Row softmax
    softmax_rows<<<dim3(SLEN, NQH), 256>>>(scores);

    // 5) attn = P @ V (causal K clamp), written into [2048, 32*128] layout
    sgemm<false, false, true><<<dim3(1, SLEN / 128, NQH), 256>>>(
        scores, SLEN, (long)SLEN * SLEN,
        qkv + (NQH + NKVH) * HDIM, QKVN, HDIM, 4,
        attn, HID, HDIM,
        SLEN, HDIM, SLEN, 1.f);

    // 6) Output projection: [2048,4096] @ [4096,4096]
    sgemm<false, false, false><<<dim3(HID / 128, SLEN / 128, 1), 256>>>(
        attn, HID, 0, Wo, HID, 0, 1, out, HID, 0, SLEN, HID, HID, 1.f);
}